// round 1
// baseline (speedup 1.0000x reference)
#include <cuda_runtime.h>
#include <math.h>
#include <stdint.h>

#define B   32
#define LQ  64
#define E   512
#define NF  10
#define FL  40
#define NFL 400      // NF*FL
#define D   512
#define H   512
#define A   512
#define R   1024
#define V   50257

typedef unsigned long long u64;

__device__ __forceinline__ u64 ffma2(u64 a, u64 b, u64 c) {
    u64 d;
    asm("fma.rn.f32x2 %0, %1, %2, %3;" : "=l"(d) : "l"(a), "l"(b), "l"(c));
    return d;
}
__device__ __forceinline__ u64 pack2(float x, float y) {
    u64 d; asm("mov.b64 %0, {%1, %2};" : "=l"(d) : "f"(x), "f"(y)); return d;
}
__device__ __forceinline__ void unpack2(u64 a, float& x, float& y) {
    asm("mov.b64 {%0, %1}, %2;" : "=f"(x), "=f"(y) : "l"(a));
}
__device__ __forceinline__ float sigmoidf_(float x) { return 1.0f / (1.0f + expf(-x)); }

// ---------------- scratch (device globals; no allocation allowed) ----------
__device__ float g_hqdec[B * A];
__device__ float g_hfdec[B * A];
__device__ float g_qscores[B * LQ];
__device__ float g_fscores[B * NFL];
__device__ float g_qvec[B * E];
__device__ float g_x[B * (E + D + E)];     // [prev_emb | f_vec | q_vec]
__device__ float g_z[2][B * 4 * H];        // two k-split partials
__device__ float g_h[B * H];
__device__ float g_r[2][B * R];
__device__ float g_m[B * (R / 2)];

// output layout offsets (concat of logits, h, c, q_vec, q_logits)
#define O_H   ((long long)B * V)
#define O_C   (O_H + (long long)B * H)
#define O_QV  (O_C + (long long)B * H)
#define O_QL  (O_QV + (long long)B * E)
#define O_TOT (O_QL + (long long)B * LQ)

// ============================================================================
// score_gemm: fused  scores[row] = sum_a tanh( X[row,:]@W[:,a] + hdec[b,a] ) * v[a]
// One launch covers both the question branch (blocks 0..63) and the facts
// branch (blocks 64..463). 32-row tile per block, 512 columns, K=512.
// Thread = 2 adjacent columns, 16 f32x2 row-pair accumulators (FFMA2-bound).
// ============================================================================
__global__ __launch_bounds__(256, 2)
void score_gemm(const float* __restrict__ bq, const float* __restrict__ fe,
                const float* __restrict__ Wq, const float* __restrict__ Wf,
                const float* __restrict__ vq, const float* __restrict__ vf)
{
    extern __shared__ float sm[];   // 512*34 floats staging, reused for reduce

    const bool isq = (blockIdx.x < (B * LQ / 32));
    const float* X; const float* W; const float* hdec; const float* v;
    float* outp; int row0, rpb;
    if (isq) {
        X = bq; W = Wq; hdec = g_hqdec; v = vq; outp = g_qscores;
        row0 = blockIdx.x * 32; rpb = LQ;
    } else {
        X = fe; W = Wf; hdec = g_hfdec; v = vf; outp = g_fscores;
        row0 = (blockIdx.x - B * LQ / 32) * 32; rpb = NFL;
    }

    // stage X tile transposed: sm[k*34 + r], row-pairs contiguous for LDS.64
    const float* Xb = X + (size_t)row0 * 512;
    for (int idx = threadIdx.x; idx < 32 * 512; idx += 256) {
        int r = idx >> 9, k = idx & 511;
        sm[k * 34 + r] = Xb[idx];
    }
    __syncthreads();

    const int c0 = threadIdx.x * 2;
    u64 acc0[16], acc1[16];
#pragma unroll
    for (int i = 0; i < 16; i++) { acc0[i] = 0ULL; acc1[i] = 0ULL; }

    const float* Wc = W + c0;
#pragma unroll 2
    for (int k = 0; k < 512; k++) {
        float2 w = *reinterpret_cast<const float2*>(Wc + (size_t)k * 512);
        u64 b0 = pack2(w.x, w.x);
        u64 b1 = pack2(w.y, w.y);
        const u64* xs = reinterpret_cast<const u64*>(sm + k * 34);
#pragma unroll
        for (int i = 0; i < 16; i++) {
            u64 x2 = xs[i];
            acc0[i] = ffma2(x2, b0, acc0[i]);
            acc1[i] = ffma2(x2, b1, acc1[i]);
        }
    }
    __syncthreads();   // done reading Xs; reuse smem as reduction buffer

    // epilogue: tanh(pre + hdec)*v, per-thread partial per row -> smem
    float v0 = v[c0], v1 = v[c0 + 1];
#pragma unroll
    for (int i = 0; i < 16; i++) {
        int r = 2 * i;
        int bb = (row0 + r) / rpb;            // pairs never straddle b (rpb even)
        float hc0 = hdec[bb * 512 + c0];
        float hc1 = hdec[bb * 512 + c0 + 1];
        float a0x, a0y, a1x, a1y;
        unpack2(acc0[i], a0x, a0y);
        unpack2(acc1[i], a1x, a1y);
        sm[r * 257 + threadIdx.x]       = tanhf(a0x + hc0) * v0 + tanhf(a1x + hc1) * v1;
        sm[(r + 1) * 257 + threadIdx.x] = tanhf(a0y + hc0) * v0 + tanhf(a1y + hc1) * v1;
    }
    __syncthreads();
    if (threadIdx.x < 32) {
        const float* rr = sm + threadIdx.x * 257;
        float s = 0.f;
#pragma unroll 8
        for (int j = 0; j < 256; j++) s += rr[j];
        outp[row0 + threadIdx.x] = s;
    }
}

// ============================================================================
// gemm32: out[32,N] = sum_p X_p[32,K_p] @ W_p[K_p,N]  (+ biases, added once)
// K_p must be a multiple of 512 (all uses are). 8 warps interleave K inside
// each 512-slab; gridDim.y (NKZ) splits K further across blocks writing
// disjoint partials out[kz][32][N] (summed deterministically downstream).
// Lane = 1 column, 16 f32x2 row-pair accumulators.
// ============================================================================
__global__ __launch_bounds__(256, 2)
void gemm32(const float* __restrict__ X0, const float* __restrict__ W0, int K0,
            const float* __restrict__ X1, const float* __restrict__ W1, int K1,
            const float* __restrict__ X2, const float* __restrict__ W2, int K2,
            const float* __restrict__ b0p, const float* __restrict__ b1p,
            const float* __restrict__ b2p,
            float* __restrict__ out, int N)
{
    extern __shared__ float sm[];   // staging 512*34 floats; reduce overlaps
    const int lane = threadIdx.x & 31;
    const int warp = threadIdx.x >> 5;
    const int kz = blockIdx.y, NKZ = gridDim.y;
    const int ws = kz * 8 + warp, WS = 8 * NKZ;
    const int col = blockIdx.x * 32 + lane;
    const bool cok = (col < N);

    u64 acc[16];
#pragma unroll
    for (int i = 0; i < 16; i++) acc[i] = 0ULL;

    const float* Xs_[3] = { X0, X1, X2 };
    const float* Ws_[3] = { W0, W1, W2 };
    int Ks_[3] = { K0, K1, K2 };

    for (int p = 0; p < 3; p++) {
        const float* X = Xs_[p]; const float* W = Ws_[p]; int K = Ks_[p];
        if (K == 0 || X == nullptr) continue;
        for (int s0 = 0; s0 < K; s0 += 512) {
            for (int idx = threadIdx.x; idx < 32 * 512; idx += 256) {
                int r = idx >> 9, kk = idx & 511;
                sm[kk * 34 + r] = X[(size_t)r * K + s0 + kk];
            }
            __syncthreads();
            for (int kk = ws; kk < 512; kk += WS) {
                float w = cok ? W[(size_t)(s0 + kk) * N + col] : 0.f;
                u64 bb = pack2(w, w);
                const u64* xs = reinterpret_cast<const u64*>(sm + kk * 34);
#pragma unroll
                for (int i = 0; i < 16; i++)
                    acc[i] = ffma2(xs[i], bb, acc[i]);
            }
            __syncthreads();
        }
    }

    // cross-warp reduce: RED[w][lane][row] with row dim padded to 33
    float* RED = sm;
#pragma unroll
    for (int i = 0; i < 16; i++) {
        float x, y; unpack2(acc[i], x, y);
        RED[(warp * 32 + lane) * 33 + 2 * i]     = x;
        RED[(warp * 32 + lane) * 33 + 2 * i + 1] = y;
    }
    __syncthreads();

    int c = threadIdx.x & 31;
    int colg = blockIdx.x * 32 + c;
    if (colg < N) {
        float bias = 0.f;
        if (kz == 0) {
            if (b0p) bias += b0p[colg];
            if (b1p) bias += b1p[colg];
            if (b2p) bias += b2p[colg];
        }
        float* outp = out + (size_t)kz * 32 * N;
        for (int r = (threadIdx.x >> 5); r < 32; r += 8) {
            float sv = bias;
#pragma unroll
            for (int w = 0; w < 8; w++)
                sv += RED[(w * 32 + c) * 33 + r];
            outp[(size_t)r * N + colg] = sv;
        }
    }
}

// ============================================================================
// question softmax + q_vec; also writes q_logits / q_vec outputs and copies
// prev_emb into the x buffer. One block per batch row.
// ============================================================================
__global__ void qvec_kernel(const float* __restrict__ bq,
                            const float* __restrict__ prev_emb,
                            float* __restrict__ out, int full)
{
    __shared__ float sc[LQ];
    __shared__ float w[LQ];
    int b = blockIdx.x, tid = threadIdx.x;
    if (tid < LQ) sc[tid] = g_qscores[b * LQ + tid];
    __syncthreads();
    if (tid == 0) {
        float mx = sc[0];
        for (int l = 1; l < LQ; l++) mx = fmaxf(mx, sc[l]);
        float s = 0.f;
        for (int l = 0; l < LQ; l++) { float e = expf(sc[l] - mx); w[l] = e; s += e; }
        float inv = 1.0f / s;
        for (int l = 0; l < LQ; l++) w[l] *= inv;
    }
    __syncthreads();
    if (full && tid < LQ) out[O_QL + b * LQ + tid] = sc[tid];   // mask all-true
    for (int e = tid; e < E; e += blockDim.x) {
        float a = 0.f;
        for (int l = 0; l < LQ; l++)
            a += w[l] * bq[((size_t)b * LQ + l) * E + e];
        g_x[b * 1536 + 1024 + e] = a;
        g_qvec[b * E + e] = a;
        if (full) out[O_QV + b * E + e] = a;
        g_x[b * 1536 + e] = prev_emb[b * E + e];
    }
}

// ============================================================================
// facts top-k(40/400) + softmax + weighted gather -> f_vec (into x buffer).
// Rank-based selection matches lax.top_k tie-breaking exactly. One block per b.
// ============================================================================
__global__ void ftopk_kernel(const float* __restrict__ fe)
{
    __shared__ float s[NFL];
    __shared__ unsigned char sel[NFL];
    __shared__ int idxl[FL];
    __shared__ float wsel[FL];
    int b = blockIdx.x, tid = threadIdx.x;
    for (int i = tid; i < NFL; i += 256) s[i] = g_fscores[b * NFL + i];
    __syncthreads();
    for (int i = tid; i < NFL; i += 256) {
        float si = s[i];
        int rank = 0;
        for (int j = 0; j < NFL; j++) {
            float sj = s[j];
            rank += (sj > si) || (sj == si && j < i);
        }
        sel[i] = (rank < FL) ? 1 : 0;
    }
    __syncthreads();
    if (tid == 0) {
        int pos = 0;
        float mx = -1e30f;
        for (int i = 0; i < NFL; i++) {
            if (sel[i]) idxl[pos++] = i;
            mx = fmaxf(mx, s[i]);          // global max == max of selected set
        }
        float sum = 0.f;
        for (int t = 0; t < FL; t++) {
            float e = expf(s[idxl[t]] - mx);
            wsel[t] = e; sum += e;
        }
        float inv = 1.0f / sum;
        for (int t = 0; t < FL; t++) wsel[t] *= inv;
    }
    __syncthreads();
    for (int d = tid; d < D; d += 256) {
        float a = 0.f;
        for (int t = 0; t < FL; t++)
            a += wsel[t] * fe[((size_t)b * NFL + idxl[t]) * D + d];
        g_x[b * 1536 + 512 + d] = a;
    }
}

// ============================================================================
// LSTM gates (keras order i,f,g,o) from the two z partials; writes h,c.
// ============================================================================
__global__ void lstm_gates(const float* __restrict__ c0,
                           float* __restrict__ out, int full)
{
    int idx = blockIdx.x * 256 + threadIdx.x;
    if (idx >= B * H) return;
    int b = idx >> 9, j = idx & 511;
    const float* z0 = g_z[0] + b * 2048;
    const float* z1 = g_z[1] + b * 2048;
    float zi = z0[j]        + z1[j];
    float zf = z0[512 + j]  + z1[512 + j];
    float zg = z0[1024 + j] + z1[1024 + j];
    float zo = z0[1536 + j] + z1[1536 + j];
    float c = sigmoidf_(zf) * c0[idx] + sigmoidf_(zi) * tanhf(zg);
    float h = sigmoidf_(zo) * tanhf(c);
    g_h[idx] = h;
    if (full) {
        out[O_H + idx] = h;
        out[O_C + idx] = c;
    }
}

// ============================================================================
// maxout over readout partial sums (biases already added at kz==0).
// ============================================================================
__global__ void maxout_kernel()
{
    int idx = blockIdx.x * 256 + threadIdx.x;
    if (idx >= B * (R / 2)) return;
    int b = idx >> 9, j = idx & 511;
    const float* r0 = g_r[0] + b * R;
    const float* r1 = g_r[1] + b * R;
    float ra = r0[2 * j]     + r1[2 * j];
    float rb = r0[2 * j + 1] + r1[2 * j + 1];
    g_m[idx] = fmaxf(ra, rb);
}

// ============================================================================
extern "C" void kernel_launch(void* const* d_in, const int* in_sizes, int n_in,
                              void* d_out, int out_size)
{
    const float* bq          = (const float*)d_in[0];
    const float* fe          = (const float*)d_in[1];
    const float* h0          = (const float*)d_in[2];
    const float* c0          = (const float*)d_in[3];
    const float* prev_emb    = (const float*)d_in[4];
    const float* Wq_enc      = (const float*)d_in[5];
    const float* Wq_dec      = (const float*)d_in[6];
    const float* vq          = (const float*)d_in[7];
    const float* Wf_enc      = (const float*)d_in[8];
    const float* Wf_dec      = (const float*)d_in[9];
    const float* vf          = (const float*)d_in[10];
    const float* lstm_kernel = (const float*)d_in[11];
    const float* lstm_rec    = (const float*)d_in[12];
    const float* lstm_bias   = (const float*)d_in[13];
    const float* Wr          = (const float*)d_in[14];
    const float* br          = (const float*)d_in[15];
    const float* Ur          = (const float*)d_in[16];
    const float* bu          = (const float*)d_in[17];
    const float* Vr          = (const float*)d_in[18];
    const float* bv          = (const float*)d_in[19];
    const float* Wy          = (const float*)d_in[20];
    const float* by          = (const float*)d_in[21];
    float* out = (float*)d_out;

    int full = (out_size >= (int)O_TOT) ? 1 : 0;

    const int SMEM = 512 * 34 * 4;  // 69632 bytes
    cudaFuncSetAttribute(score_gemm, cudaFuncAttributeMaxDynamicSharedMemorySize, SMEM);
    cudaFuncSetAttribute(gemm32,     cudaFuncAttributeMaxDynamicSharedMemorySize, SMEM);

    float *p_hqdec, *p_hfdec, *p_x, *p_qvec, *p_z, *p_h, *p_r, *p_m;
    cudaGetSymbolAddress((void**)&p_hqdec, g_hqdec);
    cudaGetSymbolAddress((void**)&p_hfdec, g_hfdec);
    cudaGetSymbolAddress((void**)&p_x,     g_x);
    cudaGetSymbolAddress((void**)&p_qvec,  g_qvec);
    cudaGetSymbolAddress((void**)&p_z,     g_z);
    cudaGetSymbolAddress((void**)&p_h,     g_h);
    cudaGetSymbolAddress((void**)&p_r,     g_r);
    cudaGetSymbolAddress((void**)&p_m,     g_m);

    // 1-2. decoder-state projections h0@Wq_dec, h0@Wf_dec  [32,512]
    gemm32<<<dim3(16, 1), 256, SMEM>>>(h0, Wq_dec, 512,
                                       nullptr, nullptr, 0, nullptr, nullptr, 0,
                                       nullptr, nullptr, nullptr, p_hqdec, 512);
    gemm32<<<dim3(16, 1), 256, SMEM>>>(h0, Wf_dec, 512,
                                       nullptr, nullptr, 0, nullptr, nullptr, 0,
                                       nullptr, nullptr, nullptr, p_hfdec, 512);

    // 3. fused attention-score GEMMs (q: 64 blocks, f: 400 blocks)
    score_gemm<<<464, 256, SMEM>>>(bq, fe, Wq_enc, Wf_enc, vq, vf);

    // 4. question softmax + q_vec (+ q_logits/q_vec outputs, prev_emb copy)
    qvec_kernel<<<B, 256>>>(bq, prev_emb, out, full);

    // 5. facts top-k + softmax + gather -> f_vec
    ftopk_kernel<<<B, 256>>>(fe);

    // 6. LSTM pre-activations z = x@kernel + h0@rec + bias (k-split 2)
    gemm32<<<dim3(64, 2), 256, SMEM>>>(p_x, lstm_kernel, 1536,
                                       h0, lstm_rec, 512,
                                       nullptr, nullptr, 0,
                                       lstm_bias, nullptr, nullptr, p_z, 2048);

    // 7. gates -> h, c
    lstm_gates<<<64, 256>>>(c0, out, full);

    // 8. readout r = h@Wr + x@Ur + q_vec@Vr + biases (k-split 2)
    gemm32<<<dim3(32, 2), 256, SMEM>>>(p_h, Wr, 512,
                                       p_x, Ur, 1536,
                                       p_qvec, Vr, 512,
                                       br, bu, bv, p_r, 1024);

    // 9. maxout -> m [32, 512]
    maxout_kernel<<<64, 256>>>();

    // 10. vocab projection logits = m@Wy + by  [32, 50257]
    gemm32<<<dim3((V + 31) / 32, 1), 256, SMEM>>>(p_m, Wy, 512,
                                                  nullptr, nullptr, 0,
                                                  nullptr, nullptr, 0,
                                                  by, nullptr, nullptr, out, V);
}

// round 2
// speedup vs baseline: 1.2339x; 1.2339x over previous
#include <cuda_runtime.h>
#include <math.h>
#include <stdint.h>

#define B   32
#define LQ  64
#define E   512
#define NF  10
#define FL  40
#define NFL 400      // NF*FL
#define D   512
#define H   512
#define A   512
#define R   1024
#define V   50257

typedef unsigned long long u64;

__device__ __forceinline__ u64 ffma2(u64 a, u64 b, u64 c) {
    u64 d;
    asm("fma.rn.f32x2 %0, %1, %2, %3;" : "=l"(d) : "l"(a), "l"(b), "l"(c));
    return d;
}
__device__ __forceinline__ u64 fadd2(u64 a, u64 b) {
    u64 d;
    asm("add.rn.f32x2 %0, %1, %2;" : "=l"(d) : "l"(a), "l"(b));
    return d;
}
__device__ __forceinline__ u64 pack2(float x, float y) {
    u64 d; asm("mov.b64 %0, {%1, %2};" : "=l"(d) : "f"(x), "f"(y)); return d;
}
__device__ __forceinline__ void unpack2(u64 a, float& x, float& y) {
    asm("mov.b64 {%0, %1}, %2;" : "=f"(x), "=f"(y) : "l"(a));
}
__device__ __forceinline__ float sigmoidf_(float x) { return 1.0f / (1.0f + expf(-x)); }

// ---------------- scratch (device globals; no allocation allowed) ----------
__device__ float g_hqdec[B * A];
__device__ float g_hfdec[B * A];
__device__ float g_qscores[B * LQ];
__device__ float g_fscores[B * NFL];
__device__ float g_qvec[B * E];
__device__ float g_x[B * (E + D + E)];     // [prev_emb | f_vec | q_vec]
__device__ float g_z[2][B * 4 * H];        // two k-split partials
__device__ float g_h[B * H];
__device__ float g_r[2][B * R];
__device__ float g_m[B * (R / 2)];

// output layout offsets (concat of logits, h, c, q_vec, q_logits)
#define O_H   ((long long)B * V)
#define O_C   (O_H + (long long)B * H)
#define O_QV  (O_C + (long long)B * H)
#define O_QL  (O_QV + (long long)B * E)
#define O_TOT (O_QL + (long long)B * LQ)

#define XSTRIDE 36     // floats per k-row in staged X (16B aligned, pad)

// ============================================================================
// hproj: both decoder-state projections in one launch.
// out[b, a] = h0[b,:] @ Wdec[:, a], a in [0,1024) split q/f.
// grid 128, block 256: block = (b, quarter of 1024 a-columns).
// ============================================================================
__global__ void hproj_kernel(const float* __restrict__ h0,
                             const float* __restrict__ Wq_dec,
                             const float* __restrict__ Wf_dec)
{
    __shared__ float hs[512];
    int bx = blockIdx.x;
    int b = bx >> 2;
    int a = (bx & 3) * 256 + threadIdx.x;      // 0..1023
    for (int i = threadIdx.x; i < 512; i += 256) hs[i] = h0[b * 512 + i];
    __syncthreads();
    const float* W; float* outp; int ai;
    if (a < 512) { W = Wq_dec; outp = g_hqdec; ai = a; }
    else         { W = Wf_dec; outp = g_hfdec; ai = a - 512; }
    float ac0 = 0.f, ac1 = 0.f, ac2 = 0.f, ac3 = 0.f;
#pragma unroll 4
    for (int k = 0; k < 512; k += 4) {
        ac0 += hs[k]     * W[(size_t)k * 512 + ai];
        ac1 += hs[k + 1] * W[(size_t)(k + 1) * 512 + ai];
        ac2 += hs[k + 2] * W[(size_t)(k + 2) * 512 + ai];
        ac3 += hs[k + 3] * W[(size_t)(k + 3) * 512 + ai];
    }
    outp[b * 512 + ai] = (ac0 + ac1) + (ac2 + ac3);
}

// ============================================================================
// score_gemm v2: scores[row] = sum_a tanh( X[row,:]@W[:,a] + hdec[b,a] ) * v[a]
// Blocks 0..63 = question branch, 64..463 = facts branch. 32-row tile.
// Thread = 4 cols x 8 row-pairs (2 row-groups of 16 rows each).
// Per k: 1 LDG.128 (W), 4 LDS.128 (X pairs), 32 FFMA2 -> FMA-pipe bound.
// ============================================================================
__global__ __launch_bounds__(256, 2)
void score_gemm(const float* __restrict__ bq, const float* __restrict__ fe,
                const float* __restrict__ Wq, const float* __restrict__ Wf,
                const float* __restrict__ vq, const float* __restrict__ vf)
{
    extern __shared__ float sm[];   // 512*36 floats staging; reused for reduce

    const bool isq = (blockIdx.x < (B * LQ / 32));
    const float* X; const float* W; const float* hdec; const float* v;
    float* outp; int row0, rpb;
    if (isq) {
        X = bq; W = Wq; hdec = g_hqdec; v = vq; outp = g_qscores;
        row0 = blockIdx.x * 32; rpb = LQ;
    } else {
        X = fe; W = Wf; hdec = g_hfdec; v = vf; outp = g_fscores;
        row0 = (blockIdx.x - B * LQ / 32) * 32; rpb = NFL;
    }

    // stage X tile transposed: sm[k*36 + r]
    const float* Xb = X + (size_t)row0 * 512;
    for (int idx = threadIdx.x; idx < 32 * 512; idx += 256) {
        int r = idx >> 9, k = idx & 511;
        sm[k * XSTRIDE + r] = Xb[idx];
    }
    __syncthreads();

    const int g  = threadIdx.x >> 7;      // row-group 0..1 (16 rows each)
    const int ct = threadIdx.x & 127;     // col-thread: cols 4*ct..4*ct+3
    const int c0 = ct * 4;

    u64 acc[32];
#pragma unroll
    for (int i = 0; i < 32; i++) acc[i] = 0ULL;

    const float4* wp = reinterpret_cast<const float4*>(W) + ct;   // stride 128 float4/k
    const float*  xp = sm + g * 16;

#pragma unroll 2
    for (int k = 0; k < 512; k++) {
        float4 w = wp[(size_t)k * 128];
        u64 b0 = pack2(w.x, w.x);
        u64 b1 = pack2(w.y, w.y);
        u64 b2 = pack2(w.z, w.z);
        u64 b3 = pack2(w.w, w.w);
        const ulonglong2* xq = reinterpret_cast<const ulonglong2*>(xp + k * XSTRIDE);
        ulonglong2 t0 = xq[0], t1 = xq[1], t2 = xq[2], t3 = xq[3];
        u64 x[8] = { t0.x, t0.y, t1.x, t1.y, t2.x, t2.y, t3.x, t3.y };
#pragma unroll
        for (int p = 0; p < 8; p++) {
            acc[p * 4 + 0] = ffma2(x[p], b0, acc[p * 4 + 0]);
            acc[p * 4 + 1] = ffma2(x[p], b1, acc[p * 4 + 1]);
            acc[p * 4 + 2] = ffma2(x[p], b2, acc[p * 4 + 2]);
            acc[p * 4 + 3] = ffma2(x[p], b3, acc[p * 4 + 3]);
        }
    }
    __syncthreads();   // done reading staged X; reuse smem as reduction buffer

    // epilogue: per-row partial = sum_{4 cols} tanh(pre + hdec)*v
    float vv0 = v[c0], vv1 = v[c0 + 1], vv2 = v[c0 + 2], vv3 = v[c0 + 3];
#pragma unroll
    for (int p = 0; p < 8; p++) {
        int r = g * 16 + 2 * p;                  // even row in pair
        int bb = (row0 + r) / rpb;               // pairs never straddle b (rpb even)
        const float* hd = hdec + bb * 512 + c0;
        float h0_ = hd[0], h1_ = hd[1], h2_ = hd[2], h3_ = hd[3];
        float lo, hi, se = 0.f, so = 0.f;
        unpack2(acc[p * 4 + 0], lo, hi); se += tanhf(lo + h0_) * vv0; so += tanhf(hi + h0_) * vv0;
        unpack2(acc[p * 4 + 1], lo, hi); se += tanhf(lo + h1_) * vv1; so += tanhf(hi + h1_) * vv1;
        unpack2(acc[p * 4 + 2], lo, hi); se += tanhf(lo + h2_) * vv2; so += tanhf(hi + h2_) * vv2;
        unpack2(acc[p * 4 + 3], lo, hi); se += tanhf(lo + h3_) * vv3; so += tanhf(hi + h3_) * vv3;
        sm[r * 133 + ct]       = se;
        sm[(r + 1) * 133 + ct] = so;
    }
    __syncthreads();
    if (threadIdx.x < 32) {
        const float* rr = sm + threadIdx.x * 133;
        float s = 0.f;
#pragma unroll 8
        for (int j = 0; j < 128; j++) s += rr[j];
        outp[row0 + threadIdx.x] = s;
    }
}

// ============================================================================
// logits_gemm: out[32, V] = m[32,512] @ Wy[512, V] + by.  Block = 32 x 256 cols.
// Thread = 4 cols x 8 row-pairs, 2-way internal k-split with smem reduce.
// ============================================================================
__global__ __launch_bounds__(256, 2)
void logits_gemm(const float* __restrict__ M, const float* __restrict__ Wy,
                 const float* __restrict__ by, float* __restrict__ out)
{
    extern __shared__ float sm[];   // stage 512*36 floats; then u64 red buffer

    for (int idx = threadIdx.x; idx < 32 * 512; idx += 256) {
        int r = idx >> 9, k = idx & 511;
        sm[k * XSTRIDE + r] = M[idx];
    }
    __syncthreads();

    const int ks = threadIdx.x >> 7;         // k-slice 0..1
    const int g  = (threadIdx.x >> 6) & 1;   // row-group 0..1
    const int ct = threadIdx.x & 63;         // col-thread: 4 cols
    const int col0 = blockIdx.x * 256 + ct * 4;

    u64 acc[32];
#pragma unroll
    for (int i = 0; i < 32; i++) acc[i] = 0ULL;

    const bool k0 = (col0 + 0) < V, k1 = (col0 + 1) < V,
               k2 = (col0 + 2) < V, k3 = (col0 + 3) < V;
    const float* xp = sm + g * 16;
    const int kbeg = ks * 256, kend = kbeg + 256;

#pragma unroll 2
    for (int k = kbeg; k < kend; k++) {
        const float* wr = Wy + (size_t)k * V + col0;
        float w0 = k0 ? wr[0] : 0.f;
        float w1 = k1 ? wr[1] : 0.f;
        float w2 = k2 ? wr[2] : 0.f;
        float w3 = k3 ? wr[3] : 0.f;
        u64 b0 = pack2(w0, w0), b1 = pack2(w1, w1), b2 = pack2(w2, w2), b3 = pack2(w3, w3);
        const ulonglong2* xq = reinterpret_cast<const ulonglong2*>(xp + k * XSTRIDE);
        ulonglong2 t0 = xq[0], t1 = xq[1], t2 = xq[2], t3 = xq[3];
        u64 x[8] = { t0.x, t0.y, t1.x, t1.y, t2.x, t2.y, t3.x, t3.y };
#pragma unroll
        for (int p = 0; p < 8; p++) {
            acc[p * 4 + 0] = ffma2(x[p], b0, acc[p * 4 + 0]);
            acc[p * 4 + 1] = ffma2(x[p], b1, acc[p * 4 + 1]);
            acc[p * 4 + 2] = ffma2(x[p], b2, acc[p * 4 + 2]);
            acc[p * 4 + 3] = ffma2(x[p], b3, acc[p * 4 + 3]);
        }
    }
    __syncthreads();   // staged M no longer needed

    u64* red = reinterpret_cast<u64*>(sm);   // [128][33] u64 = 33792 B
    if (ks == 1) {
        u64* rp = red + (g * 64 + ct) * 33;
#pragma unroll
        for (int i = 0; i < 32; i++) rp[i] = acc[i];
    }
    __syncthreads();
    if (ks == 0) {
        const u64* rp = red + (g * 64 + ct) * 33;
#pragma unroll
        for (int i = 0; i < 32; i++) acc[i] = fadd2(acc[i], rp[i]);

        float bb[4];
        bb[0] = k0 ? by[col0 + 0] : 0.f;
        bb[1] = k1 ? by[col0 + 1] : 0.f;
        bb[2] = k2 ? by[col0 + 2] : 0.f;
        bb[3] = k3 ? by[col0 + 3] : 0.f;
#pragma unroll
        for (int p = 0; p < 8; p++) {
            int r = g * 16 + 2 * p;
#pragma unroll
            for (int c = 0; c < 4; c++) {
                if (col0 + c < V) {
                    float lo, hi; unpack2(acc[p * 4 + c], lo, hi);
                    out[(size_t)r * V + col0 + c]       = lo + bb[c];
                    out[(size_t)(r + 1) * V + col0 + c] = hi + bb[c];
                }
            }
        }
    }
}

// ============================================================================
// gemm32 (v1, kept for the small LSTM/readout GEMMs):
// out[kz][32,N] = partial sums of sum_p X_p[32,K_p] @ W_p[K_p,N] (+ biases at kz0)
// ============================================================================
__global__ __launch_bounds__(256, 2)
void gemm32(const float* __restrict__ X0, const float* __restrict__ W0, int K0,
            const float* __restrict__ X1, const float* __restrict__ W1, int K1,
            const float* __restrict__ X2, const float* __restrict__ W2, int K2,
            const float* __restrict__ b0p, const float* __restrict__ b1p,
            const float* __restrict__ b2p,
            float* __restrict__ out, int N)
{
    extern __shared__ float sm[];
    const int lane = threadIdx.x & 31;
    const int warp = threadIdx.x >> 5;
    const int kz = blockIdx.y, NKZ = gridDim.y;
    const int ws = kz * 8 + warp, WS = 8 * NKZ;
    const int col = blockIdx.x * 32 + lane;
    const bool cok = (col < N);

    u64 acc[16];
#pragma unroll
    for (int i = 0; i < 16; i++) acc[i] = 0ULL;

    const float* Xs_[3] = { X0, X1, X2 };
    const float* Ws_[3] = { W0, W1, W2 };
    int Ks_[3] = { K0, K1, K2 };

    for (int p = 0; p < 3; p++) {
        const float* X = Xs_[p]; const float* W = Ws_[p]; int K = Ks_[p];
        if (K == 0 || X == nullptr) continue;
        for (int s0 = 0; s0 < K; s0 += 512) {
            for (int idx = threadIdx.x; idx < 32 * 512; idx += 256) {
                int r = idx >> 9, kk = idx & 511;
                sm[kk * 34 + r] = X[(size_t)r * K + s0 + kk];
            }
            __syncthreads();
            for (int kk = ws; kk < 512; kk += WS) {
                float w = cok ? W[(size_t)(s0 + kk) * N + col] : 0.f;
                u64 bb = pack2(w, w);
                const u64* xs = reinterpret_cast<const u64*>(sm + kk * 34);
#pragma unroll
                for (int i = 0; i < 16; i++)
                    acc[i] = ffma2(xs[i], bb, acc[i]);
            }
            __syncthreads();
        }
    }

    float* RED = sm;
#pragma unroll
    for (int i = 0; i < 16; i++) {
        float x, y; unpack2(acc[i], x, y);
        RED[(warp * 32 + lane) * 33 + 2 * i]     = x;
        RED[(warp * 32 + lane) * 33 + 2 * i + 1] = y;
    }
    __syncthreads();

    int c = threadIdx.x & 31;
    int colg = blockIdx.x * 32 + c;
    if (colg < N) {
        float bias = 0.f;
        if (kz == 0) {
            if (b0p) bias += b0p[colg];
            if (b1p) bias += b1p[colg];
            if (b2p) bias += b2p[colg];
        }
        float* outp = out + (size_t)kz * 32 * N;
        for (int r = (threadIdx.x >> 5); r < 32; r += 8) {
            float sv = bias;
#pragma unroll
            for (int w = 0; w < 8; w++)
                sv += RED[(w * 32 + c) * 33 + r];
            outp[(size_t)r * N + colg] = sv;
        }
    }
}

// ============================================================================
// question softmax + q_vec (parallel). One block of 512 threads per batch row.
// ============================================================================
__global__ void qvec_kernel(const float* __restrict__ bq,
                            const float* __restrict__ prev_emb,
                            float* __restrict__ out, int full)
{
    __shared__ float sc[LQ];
    __shared__ float w[LQ];
    __shared__ float sred[2];
    int b = blockIdx.x, tid = threadIdx.x;
    if (tid < LQ) sc[tid] = g_qscores[b * LQ + tid];
    __syncthreads();
    if (tid < 32) {
        float m = fmaxf(sc[tid], sc[tid + 32]);
#pragma unroll
        for (int off = 16; off > 0; off >>= 1)
            m = fmaxf(m, __shfl_xor_sync(0xffffffffu, m, off));
        if (tid == 0) sred[0] = m;
    }
    __syncthreads();
    if (tid < LQ) w[tid] = expf(sc[tid] - sred[0]);
    __syncthreads();
    if (tid < 32) {
        float s = w[tid] + w[tid + 32];
#pragma unroll
        for (int off = 16; off > 0; off >>= 1)
            s += __shfl_xor_sync(0xffffffffu, s, off);
        if (tid == 0) sred[1] = 1.0f / s;
    }
    __syncthreads();
    if (tid < LQ) w[tid] *= sred[1];
    __syncthreads();

    if (full && tid < LQ) out[O_QL + b * LQ + tid] = sc[tid];   // mask all-true

    int e = tid;                                   // 512 threads = 512 elems
    const float* bqb = bq + (size_t)b * LQ * E + e;
    float a0 = 0.f, a1 = 0.f, a2 = 0.f, a3 = 0.f;
#pragma unroll 4
    for (int l = 0; l < LQ; l += 4) {
        a0 += w[l]     * bqb[(size_t)l * E];
        a1 += w[l + 1] * bqb[(size_t)(l + 1) * E];
        a2 += w[l + 2] * bqb[(size_t)(l + 2) * E];
        a3 += w[l + 3] * bqb[(size_t)(l + 3) * E];
    }
    float a = (a0 + a1) + (a2 + a3);
    g_x[b * 1536 + 1024 + e] = a;
    g_qvec[b * E + e] = a;
    if (full) out[O_QV + b * E + e] = a;
    g_x[b * 1536 + e] = prev_emb[b * E + e];
}

// ============================================================================
// facts top-k(40/400) + softmax + gather, fully parallel.
// rank < FL is the selection; rank IS the output position (matches lax.top_k
// descending order with index tie-break). One block of 512 threads per b.
// ============================================================================
__global__ void ftopk_kernel(const float* __restrict__ fe)
{
    __shared__ float s[NFL];
    __shared__ int   idxl[FL];
    __shared__ float wn[FL];
    __shared__ float wred[16];
    __shared__ float smx, sinv;
    int b = blockIdx.x, tid = threadIdx.x;
    if (tid < NFL) s[tid] = g_fscores[b * NFL + tid];
    __syncthreads();

    // block max over 400
    {
        float m = (tid < NFL) ? s[tid] : -1e30f;
#pragma unroll
        for (int off = 16; off > 0; off >>= 1)
            m = fmaxf(m, __shfl_xor_sync(0xffffffffu, m, off));
        if ((tid & 31) == 0) wred[tid >> 5] = m;
        __syncthreads();
        if (tid < 16) {
            float m2 = wred[tid];
#pragma unroll
            for (int off = 8; off > 0; off >>= 1)
                m2 = fmaxf(m2, __shfl_xor_sync(0xffffu, m2, off));
            if (tid == 0) smx = m2;
        }
    }
    __syncthreads();

    if (tid < NFL) {
        float si = s[tid];
        int rank = 0;
        for (int j = 0; j < NFL; j++) {
            float sj = s[j];
            rank += (sj > si) || (sj == si && j < tid);
        }
        if (rank < FL) {
            idxl[rank] = tid;
            wn[rank] = expf(si - smx);
        }
    }
    __syncthreads();
    if (tid < 32) {
        float v = wn[tid] + ((tid < FL - 32) ? wn[tid + 32] : 0.f);
#pragma unroll
        for (int off = 16; off > 0; off >>= 1)
            v += __shfl_xor_sync(0xffffffffu, v, off);
        if (tid == 0) sinv = 1.0f / v;
    }
    __syncthreads();
    if (tid < FL) wn[tid] *= sinv;
    __syncthreads();

    int d = tid;                                  // 512 threads = D
    float a = 0.f;
#pragma unroll 8
    for (int t = 0; t < FL; t++)
        a += wn[t] * fe[((size_t)b * NFL + idxl[t]) * D + d];
    g_x[b * 1536 + 512 + d] = a;
}

// ============================================================================
// LSTM gates (keras order i,f,g,o) from the two z partials; writes h,c.
// ============================================================================
__global__ void lstm_gates(const float* __restrict__ c0,
                           float* __restrict__ out, int full)
{
    int idx = blockIdx.x * 256 + threadIdx.x;
    if (idx >= B * H) return;
    int b = idx >> 9, j = idx & 511;
    const float* z0 = g_z[0] + b * 2048;
    const float* z1 = g_z[1] + b * 2048;
    float zi = z0[j]        + z1[j];
    float zf = z0[512 + j]  + z1[512 + j];
    float zg = z0[1024 + j] + z1[1024 + j];
    float zo = z0[1536 + j] + z1[1536 + j];
    float c = sigmoidf_(zf) * c0[idx] + sigmoidf_(zi) * tanhf(zg);
    float h = sigmoidf_(zo) * tanhf(c);
    g_h[idx] = h;
    if (full) {
        out[O_H + idx] = h;
        out[O_C + idx] = c;
    }
}

// ============================================================================
// maxout over readout partial sums (biases already added at kz==0).
// ============================================================================
__global__ void maxout_kernel()
{
    int idx = blockIdx.x * 256 + threadIdx.x;
    if (idx >= B * (R / 2)) return;
    int b = idx >> 9, j = idx & 511;
    const float* r0 = g_r[0] + b * R;
    const float* r1 = g_r[1] + b * R;
    float ra = r0[2 * j]     + r1[2 * j];
    float rb = r0[2 * j + 1] + r1[2 * j + 1];
    g_m[idx] = fmaxf(ra, rb);
}

// ============================================================================
extern "C" void kernel_launch(void* const* d_in, const int* in_sizes, int n_in,
                              void* d_out, int out_size)
{
    const float* bq          = (const float*)d_in[0];
    const float* fe          = (const float*)d_in[1];
    const float* h0          = (const float*)d_in[2];
    const float* c0          = (const float*)d_in[3];
    const float* prev_emb    = (const float*)d_in[4];
    const float* Wq_enc      = (const float*)d_in[5];
    const float* Wq_dec      = (const float*)d_in[6];
    const float* vq          = (const float*)d_in[7];
    const float* Wf_enc      = (const float*)d_in[8];
    const float* Wf_dec      = (const float*)d_in[9];
    const float* vf          = (const float*)d_in[10];
    const float* lstm_kernel = (const float*)d_in[11];
    const float* lstm_rec    = (const float*)d_in[12];
    const float* lstm_bias   = (const float*)d_in[13];
    const float* Wr          = (const float*)d_in[14];
    const float* br          = (const float*)d_in[15];
    const float* Ur          = (const float*)d_in[16];
    const float* bu          = (const float*)d_in[17];
    const float* Vr          = (const float*)d_in[18];
    const float* bv          = (const float*)d_in[19];
    const float* Wy          = (const float*)d_in[20];
    const float* by          = (const float*)d_in[21];
    float* out = (float*)d_out;

    int full = (out_size >= (int)O_TOT) ? 1 : 0;

    const int SMEM_BIG = 512 * XSTRIDE * 4;   // 73728 B for score/logits
    const int SMEM_G32 = 512 * 34 * 4;        // 69632 B for gemm32
    cudaFuncSetAttribute(score_gemm,  cudaFuncAttributeMaxDynamicSharedMemorySize, SMEM_BIG);
    cudaFuncSetAttribute(logits_gemm, cudaFuncAttributeMaxDynamicSharedMemorySize, SMEM_BIG);
    cudaFuncSetAttribute(gemm32,      cudaFuncAttributeMaxDynamicSharedMemorySize, SMEM_G32);

    float *p_x, *p_qvec, *p_z, *p_h, *p_r, *p_m;
    cudaGetSymbolAddress((void**)&p_x,    g_x);
    cudaGetSymbolAddress((void**)&p_qvec, g_qvec);
    cudaGetSymbolAddress((void**)&p_z,    g_z);
    cudaGetSymbolAddress((void**)&p_h,    g_h);
    cudaGetSymbolAddress((void**)&p_r,    g_r);
    cudaGetSymbolAddress((void**)&p_m,    g_m);

    // 1. decoder-state projections (both in one launch)
    hproj_kernel<<<128, 256>>>(h0, Wq_dec, Wf_dec);

    // 2. fused attention-score GEMMs (q: 64 blocks, f: 400 blocks)
    score_gemm<<<464, 256, SMEM_BIG>>>(bq, fe, Wq_enc, Wf_enc, vq, vf);

    // 3. question softmax + q_vec (+ outputs, prev_emb copy)
    qvec_kernel<<<B, 512>>>(bq, prev_emb, out, full);

    // 4. facts top-k + softmax + gather -> f_vec
    ftopk_kernel<<<B, 512>>>(fe);

    // 5. LSTM pre-activations z = x@kernel + h0@rec + bias (k-split 2)
    gemm32<<<dim3(64, 2), 256, SMEM_G32>>>(p_x, lstm_kernel, 1536,
                                           h0, lstm_rec, 512,
                                           nullptr, nullptr, 0,
                                           lstm_bias, nullptr, nullptr, p_z, 2048);

    // 6. gates -> h, c
    lstm_gates<<<64, 256>>>(c0, out, full);

    // 7. readout r = h@Wr + x@Ur + q_vec@Vr + biases (k-split 2)
    gemm32<<<dim3(32, 2), 256, SMEM_G32>>>(p_h, Wr, 512,
                                           p_x, Ur, 1536,
                                           p_qvec, Vr, 512,
                                           br, bu, bv, p_r, 1024);

    // 8. maxout -> m [32, 512]
    maxout_kernel<<<64, 256>>>();

    // 9. vocab projection logits = m@Wy + by  [32, 50257]
    logits_gemm<<<(V + 255) / 256, 256, SMEM_BIG>>>(p_m, Wy, by, out);
}